// round 5
// baseline (speedup 1.0000x reference)
#include <cuda_runtime.h>
#include <cuda_bf16.h>
#include <math.h>

#define Bsz 512
#define Ssz 512
#define Tsz 128
#define NEGV -10000.0f

// scratch (no allocations allowed)
__device__ float g_fwd[Bsz];
__device__ float g_gold[Bsz];
__device__ int   g_len[Bsz];
__device__ int   g_order[Bsz];
__device__ int   g_slen[Bsz];

// ---- packed f32x2 helpers (sm_100+) ----
__device__ __forceinline__ unsigned long long pack2(float lo, float hi) {
    unsigned long long r;
    asm("mov.b64 %0, {%1, %2};" : "=l"(r) : "f"(lo), "f"(hi));
    return r;
}
__device__ __forceinline__ void ffma2(unsigned long long& d,
                                      unsigned long long a,
                                      unsigned long long b) {
    asm("fma.rn.f32x2 %0, %1, %2, %0;" : "+l"(d) : "l"(a), "l"(b));
}
__device__ __forceinline__ unsigned long long addp(unsigned long long a,
                                                   unsigned long long b) {
    unsigned long long r;
    asm("add.rn.f32x2 %0, %1, %2;" : "=l"(r) : "l"(a), "l"(b));
    return r;
}
__device__ __forceinline__ float unpack_sum(unsigned long long a) {
    float lo, hi;
    asm("mov.b64 {%0, %1}, %2;" : "=f"(lo), "=f"(hi) : "l"(a));
    return lo + hi;
}

// ---------------------------------------------------------------------------
// Kernel 1: lengths
// ---------------------------------------------------------------------------
__global__ __launch_bounds__(128)
void crf_len_kernel(const float* __restrict__ mask)
{
    __shared__ float sh[4];
    const int b = blockIdx.x, tid = threadIdx.x;
    const int warp = tid >> 5, lane = tid & 31;
    const float4* mb = reinterpret_cast<const float4*>(mask + (size_t)b * Ssz);
    float4 v = mb[tid];
    float s = v.x + v.y + v.z + v.w;
    #pragma unroll
    for (int off = 16; off > 0; off >>= 1)
        s += __shfl_xor_sync(0xffffffffu, s, off);
    if (lane == 0) sh[warp] = s;
    __syncthreads();
    if (tid == 0)
        g_len[b] = (int)(sh[0] + sh[1] + sh[2] + sh[3] + 0.5f);
}

// ---------------------------------------------------------------------------
// Kernel 2: bitonic sort 512 keys, descending by len
// ---------------------------------------------------------------------------
__global__ __launch_bounds__(512)
void crf_sort_kernel()
{
    __shared__ int keys[Bsz];
    const int tid = threadIdx.x;
    keys[tid] = (g_len[tid] << 16) | tid;
    __syncthreads();
    for (int k = 2; k <= Bsz; k <<= 1) {
        for (int j = k >> 1; j > 0; j >>= 1) {
            int ixj = tid ^ j;
            if (ixj > tid) {
                int a = keys[tid];
                int b2 = keys[ixj];
                bool up = ((tid & k) == 0);
                if (up ? (a < b2) : (a > b2)) {
                    keys[tid] = b2;
                    keys[ixj] = a;
                }
            }
            __syncthreads();
        }
    }
    g_order[tid] = keys[tid] & 0xFFFF;
    g_slen[tid]  = keys[tid] >> 16;
}

// ---------------------------------------------------------------------------
// Kernel 3: forward + gold. One CTA (256 threads) per sorted batch.
// Two threads per E-row: thread (r = tid>>1, h = tid&1) holds
// exp(trans[r][h*64 .. h*64+63]) as 32 f32x2 registers.
// State: p_i = exp(alpha_i - C) in SMEM, scalar shift increment d published
// one step stale by thread 0, C accumulated per-thread.
// Per step:  s_r = E[r]·p  (half-sums combined via shfl_xor(1)),
//            p'_r = s_r * exp(x_t[r] - d)   [exp computed off-chain],
//            thread0 publishes d_next = log(s_0) + x_t[0],  C += d.
// ONE barrier per step; p/d double-buffered. No log/exp on the critical
// chain except thread0's log. alpha reconstructed at the end: log(p)+C.
// ---------------------------------------------------------------------------
__global__ __launch_bounds__(256, 2)
void crf_forward_kernel(const float* __restrict__ x,
                        const int*   __restrict__ tags,
                        const float* __restrict__ trans)
{
    __shared__ __align__(16) float sh_p[2][Tsz];
    __shared__ float sh_d[2];
    __shared__ float sh_red[8];

    const int tid  = threadIdx.x;
    const int lane = tid & 31;
    const int warp = tid >> 5;
    const int r    = tid >> 1;        // row 0..127
    const int h    = tid & 1;         // half 0/1
    const int b    = g_order[blockIdx.x];
    const int len  = g_slen[blockIdx.x];

    // E half-row: e2[2k],e2[2k+1] cover trans[r][h*64 + 4k .. +3]
    unsigned long long e2[32];
    const float4* trow = reinterpret_cast<const float4*>(trans + r * Tsz + h * 64);
    #pragma unroll
    for (int q = 0; q < 16; q++) {
        float4 v4 = trow[q];
        e2[2*q    ] = pack2(__expf(v4.x), __expf(v4.y));
        e2[2*q + 1] = pack2(__expf(v4.z), __expf(v4.w));
    }

    // init: p = exp(alpha0), C = 0, d = 0
    if (h == 0) sh_p[0][r] = (r == 0) ? 1.0f : 0.0f;   // exp(0), exp(-10000)->0
    if (tid == 0) sh_d[0] = 0.0f;
    float C = 0.0f;
    float pn = (r == 0) ? 1.0f : 0.0f;                 // last p (for len==0 safety)

    const float* xb = x + (size_t)b * Ssz * Tsz;
    float xr = __ldg(xb + r);                          // x for t = 0
    __syncthreads();

    for (int t = 0; t < len; t++) {
        const int buf = t & 1;
        float d = sh_d[buf];
        float w = __expf(xr - d);                      // off critical chain
        // prefetch next x unconditionally (t+1 <= len <= 510 < 512: row exists)
        float xn = __ldg(xb + (size_t)(t + 1) * Tsz + r);

        const ulonglong2* p2 =
            reinterpret_cast<const ulonglong2*>(sh_p[buf] + h * 64);
        unsigned long long a0=0ull, a1=0ull, a2=0ull, a3=0ull;
        #pragma unroll
        for (int q = 0; q < 16; q += 2) {
            ulonglong2 u0 = p2[q];
            ulonglong2 u1 = p2[q + 1];
            ffma2(a0, e2[2*q + 0], u0.x);
            ffma2(a1, e2[2*q + 1], u0.y);
            ffma2(a2, e2[2*q + 2], u1.x);
            ffma2(a3, e2[2*q + 3], u1.y);
        }
        float sh_half = unpack_sum(addp(addp(a0, a1), addp(a2, a3)));
        float s = sh_half + __shfl_xor_sync(0xffffffffu, sh_half, 1);

        pn = s * w;                                    // p' = exp(alpha_new - C_new)
        if (h == 0) sh_p[buf ^ 1][r] = pn;
        if (tid == 0) sh_d[buf ^ 1] = __logf(s) + xr;  // d for next step (stale)
        C += d;
        xr = xn;
        __syncthreads();                               // ONE barrier per step
    }

    // ---- final: fwd[b] = LSE_r(log(pn) + C + trans[END=1][r]) ----
    // rows are duplicated across the two halves; h==1 contributes 0 to the sum.
    float v = __logf(pn) + C + __ldg(trans + 1 * Tsz + r);
    float wm = v;
    #pragma unroll
    for (int off = 16; off > 0; off >>= 1)
        wm = fmaxf(wm, __shfl_xor_sync(0xffffffffu, wm, off));
    if (lane == 0) sh_red[warp] = wm;
    __syncthreads();
    float m = sh_red[0];
    #pragma unroll
    for (int k = 1; k < 8; k++) m = fmaxf(m, sh_red[k]);

    float ws = (h == 0) ? __expf(v - m) : 0.0f;
    #pragma unroll
    for (int off = 16; off > 0; off >>= 1)
        ws += __shfl_xor_sync(0xffffffffu, ws, off);
    __syncthreads();
    if (lane == 0) sh_red[warp] = ws;
    __syncthreads();
    if (tid == 0) {
        float tot = 0.f;
        #pragma unroll
        for (int k = 0; k < 8; k++) tot += sh_red[k];
        g_fwd[b] = m + __logf(tot);
    }

    // ---- gold score (mask==1 <=> t < len) ----
    const int* tg = tags + (size_t)b * Ssz;
    float acc = 0.0f;
    for (int t2 = tid; t2 < len; t2 += 256) {
        int tnext = tg[t2 + 1];
        int tcur  = tg[t2];
        acc += xb[(size_t)t2 * Tsz + tnext] + __ldg(trans + tnext * Tsz + tcur);
    }
    #pragma unroll
    for (int off = 16; off > 0; off >>= 1)
        acc += __shfl_xor_sync(0xffffffffu, acc, off);
    __syncthreads();
    if (lane == 0) sh_red[warp] = acc;
    __syncthreads();
    if (tid == 0) {
        float total = 0.f;
        #pragma unroll
        for (int k = 0; k < 8; k++) total += sh_red[k];
        g_gold[b] = total + __ldg(trans + 1 * Tsz + tg[len]);   // END_ID = 1
    }
}

// ---------------------------------------------------------------------------
// Kernel 4: out[0] = mean(fwd - gold)
// ---------------------------------------------------------------------------
__global__ __launch_bounds__(512)
void crf_reduce_kernel(float* __restrict__ out)
{
    __shared__ float sh[16];
    const int tid  = threadIdx.x;
    const int warp = tid >> 5;
    const int lane = tid & 31;

    float d = g_fwd[tid] - g_gold[tid];
    #pragma unroll
    for (int off = 16; off > 0; off >>= 1)
        d += __shfl_xor_sync(0xffffffffu, d, off);
    if (lane == 0) sh[warp] = d;
    __syncthreads();
    if (warp == 0) {
        float v = (lane < 16) ? sh[lane] : 0.0f;
        #pragma unroll
        for (int off = 8; off > 0; off >>= 1)
            v += __shfl_xor_sync(0xffffffffu, v, off);
        if (lane == 0) out[0] = v * (1.0f / (float)Bsz);
    }
}

extern "C" void kernel_launch(void* const* d_in, const int* in_sizes, int n_in,
                              void* d_out, int out_size)
{
    const float* x     = (const float*)d_in[0];
    const int*   tags  = (const int*)  d_in[1];
    const float* mask  = (const float*)d_in[2];
    const float* trans = (const float*)d_in[3];
    float* out = (float*)d_out;

    crf_len_kernel    <<<Bsz, 128>>>(mask);
    crf_sort_kernel   <<<1,   512>>>();
    crf_forward_kernel<<<Bsz, 256>>>(x, tags, trans);
    crf_reduce_kernel <<<1,   512>>>(out);
}